// round 5
// baseline (speedup 1.0000x reference)
#include <cuda_runtime.h>

// Problem constants (MoE_TopK: E=16, K=2, B=4096, D_IN=1024, D_HID=2048, D_OUT=1024)
#define NTOK  4096
#define NEXP  16
#define KSEL  2
#define DIN   1024
#define DHID  2048
#define DOUT  1024
#define CAP   4096   // worst-case tokens per expert

// Scratch (no allocations allowed -> __device__ globals, .bss)
__device__ int   g_cnt[NEXP];
__device__ int   g_tok[NEXP * CAP];
__device__ int   g_slot[NEXP * CAP];
__device__ float g_tw[NTOK * KSEL];
__device__ float g_h[NTOK * KSEL * DHID];   // 64 MB
__device__ float g_y[NTOK * KSEL * DOUT];   // 32 MB

// ---------------------------------------------------------------------------
// 0) zero the per-expert counters (must happen every launch: graph replays)
// ---------------------------------------------------------------------------
__global__ void init_kernel() {
    if (threadIdx.x < NEXP) g_cnt[threadIdx.x] = 0;
}

// ---------------------------------------------------------------------------
// 1) gating: scores = x @ gate_w^T, top-2, softmax over the 2, route.
//    one block per token, 128 threads
// ---------------------------------------------------------------------------
__global__ __launch_bounds__(128)
void gate_kernel(const float* __restrict__ x, const float* __restrict__ gw) {
    __shared__ float xs[DIN];
    __shared__ float sc[NEXP];

    const int b = blockIdx.x;
    const float4* xg  = (const float4*)(x + (size_t)b * DIN);
    float4*       xs4 = (float4*)xs;
    for (int i = threadIdx.x; i < DIN / 4; i += blockDim.x) xs4[i] = xg[i];
    __syncthreads();

    const int warp = threadIdx.x >> 5;
    const int lane = threadIdx.x & 31;
    for (int e = warp; e < NEXP; e += 4) {
        const float* w = gw + (size_t)e * DIN;
        float s = 0.f;
        for (int i = lane; i < DIN; i += 32) s += xs[i] * __ldg(&w[i]);
        #pragma unroll
        for (int o = 16; o > 0; o >>= 1) s += __shfl_xor_sync(0xffffffffu, s, o);
        if (lane == 0) sc[e] = s;
    }
    __syncthreads();

    if (threadIdx.x == 0) {
        // top-1 (first occurrence on tie, matching jax top_k tie order)
        int i0 = 0; float v0 = sc[0];
        #pragma unroll
        for (int e = 1; e < NEXP; e++) if (sc[e] > v0) { v0 = sc[e]; i0 = e; }
        // top-2
        int i1 = -1; float v1 = -3.4e38f;
        #pragma unroll
        for (int e = 0; e < NEXP; e++)
            if (e != i0 && sc[e] > v1) { v1 = sc[e]; i1 = e; }

        // softmax over (v0, v1); v0 >= v1 so it is already max-shifted
        float e1  = __expf(v1 - v0);
        float inv = 1.f / (1.f + e1);
        g_tw[b * 2 + 0] = inv;
        g_tw[b * 2 + 1] = e1 * inv;

        int p0 = atomicAdd(&g_cnt[i0], 1);
        g_tok[i0 * CAP + p0]  = b;
        g_slot[i0 * CAP + p0] = 0;
        int p1 = atomicAdd(&g_cnt[i1], 1);
        g_tok[i1 * CAP + p1]  = b;
        g_slot[i1 * CAP + p1] = 1;
    }
}

// ---------------------------------------------------------------------------
// 2)+3) grouped NT GEMM over gathered rows.
//    PHASE1:  C = relu(x[gathered] @ w1_e^T + b1_e)  -> g_h   (K=DIN,  N=DHID)
//    !PHASE1: C =      g_h[rows]  @ w2_e^T + b2_e    -> g_y   (K=DHID, N=DOUT)
//    Tile: 128x128x16, 256 threads, 8x8 per thread.
// ---------------------------------------------------------------------------
template<int KDIM, int NDIM, bool PHASE1>
__global__ __launch_bounds__(256)
void moe_gemm(const float* __restrict__ Ax,     // x (phase1) / unused (phase2)
              const float* __restrict__ W,      // [NEXP, NDIM, KDIM]
              const float* __restrict__ bias)   // [NEXP, NDIM]
{
    const int e   = blockIdx.z;
    const int n_e = g_cnt[e];
    const int m0  = blockIdx.x * 128;
    if (m0 >= n_e) return;                       // cheap early-exit for dead tiles
    const int n0  = blockIdx.y * 128;

    const float* A = PHASE1 ? Ax : g_h;
    float*       C = PHASE1 ? g_h : g_y;

    __shared__ float As[16][128];
    __shared__ float Bs[16][128];
    __shared__ int   srow[128];   // A-row index (token for phase1, r for phase2)
    __shared__ int   scrow[128];  // C-row index r = tok*2 + slot

    const int tid = threadIdx.x;

    if (tid < 128) {
        int p = m0 + tid;
        if (p < n_e) {
            int tok  = g_tok[e * CAP + p];
            int slot = g_slot[e * CAP + p];
            int r    = tok * 2 + slot;
            srow[tid]  = PHASE1 ? tok : r;
            scrow[tid] = r;
        } else {
            srow[tid]  = -1;
            scrow[tid] = -1;
        }
    }
    __syncthreads();

    const float* Wb = W + (size_t)e * NDIM * KDIM;

    float acc[8][8];
    #pragma unroll
    for (int i = 0; i < 8; i++)
        #pragma unroll
        for (int j = 0; j < 8; j++) acc[i][j] = 0.f;

    const int tn = (tid & 15) * 8;   // 0..120
    const int tm = (tid >> 4) * 8;   // 0..120

    for (int kt = 0; kt < KDIM; kt += 16) {
        // A tile: 128 rows x 16 k = 512 float4 loads, 2 per thread (gathered)
        #pragma unroll
        for (int li = 0; li < 2; li++) {
            int f  = tid + li * 256;       // 0..511
            int m  = f >> 2;               // 0..127
            int kq = (f & 3) * 4;          // 0,4,8,12
            int ar = srow[m];
            float4 v = make_float4(0.f, 0.f, 0.f, 0.f);
            if (ar >= 0)
                v = *(const float4*)(A + (size_t)ar * KDIM + kt + kq);
            As[kq + 0][m] = v.x; As[kq + 1][m] = v.y;
            As[kq + 2][m] = v.z; As[kq + 3][m] = v.w;
        }
        // B tile: 128 n-rows x 16 k
        #pragma unroll
        for (int li = 0; li < 2; li++) {
            int f  = tid + li * 256;
            int n  = f >> 2;
            int kq = (f & 3) * 4;
            float4 v = __ldg((const float4*)(Wb + (size_t)(n0 + n) * KDIM + kt + kq));
            Bs[kq + 0][n] = v.x; Bs[kq + 1][n] = v.y;
            Bs[kq + 2][n] = v.z; Bs[kq + 3][n] = v.w;
        }
        __syncthreads();

        #pragma unroll 8
        for (int kk = 0; kk < 16; kk++) {
            float4 a0 = *(const float4*)&As[kk][tm];
            float4 a1 = *(const float4*)&As[kk][tm + 4];
            float4 b0 = *(const float4*)&Bs[kk][tn];
            float4 b1 = *(const float4*)&Bs[kk][tn + 4];
            float av[8] = {a0.x, a0.y, a0.z, a0.w, a1.x, a1.y, a1.z, a1.w};
            float bw[8] = {b0.x, b0.y, b0.z, b0.w, b1.x, b1.y, b1.z, b1.w};
            #pragma unroll
            for (int i = 0; i < 8; i++)
                #pragma unroll
                for (int j = 0; j < 8; j++)
                    acc[i][j] += av[i] * bw[j];
        }
        __syncthreads();
    }

    // epilogue: hoisted vector bias load, (+relu phase1), scatter to C rows
    float4 bv0 = __ldg((const float4*)(bias + (size_t)e * NDIM + n0 + tn));
    float4 bv1 = __ldg((const float4*)(bias + (size_t)e * NDIM + n0 + tn + 4));
    const float bb[8] = {bv0.x, bv0.y, bv0.z, bv0.w, bv1.x, bv1.y, bv1.z, bv1.w};

    #pragma unroll
    for (int i = 0; i < 8; i++) {
        int cr = scrow[tm + i];
        if (cr < 0) continue;
        float* cp = C + (size_t)cr * NDIM + n0 + tn;
        float4 o0, o1;
        float v0 = acc[i][0] + bb[0], v1 = acc[i][1] + bb[1];
        float v2 = acc[i][2] + bb[2], v3 = acc[i][3] + bb[3];
        float v4 = acc[i][4] + bb[4], v5 = acc[i][5] + bb[5];
        float v6 = acc[i][6] + bb[6], v7 = acc[i][7] + bb[7];
        if (PHASE1) {
            v0 = fmaxf(v0, 0.f); v1 = fmaxf(v1, 0.f);
            v2 = fmaxf(v2, 0.f); v3 = fmaxf(v3, 0.f);
            v4 = fmaxf(v4, 0.f); v5 = fmaxf(v5, 0.f);
            v6 = fmaxf(v6, 0.f); v7 = fmaxf(v7, 0.f);
        }
        o0 = make_float4(v0, v1, v2, v3);
        o1 = make_float4(v4, v5, v6, v7);
        ((float4*)cp)[0] = o0;
        ((float4*)cp)[1] = o1;
    }
}

// ---------------------------------------------------------------------------
// 4) combine: out[b] = w0*y[b,0] + w1*y[b,1]
// ---------------------------------------------------------------------------
__global__ __launch_bounds__(256)
void combine_kernel(float* __restrict__ out) {
    int i = blockIdx.x * blockDim.x + threadIdx.x;   // float4 index
    const int per_tok = DOUT / 4;
    if (i >= NTOK * per_tok) return;
    int b = i / per_tok;
    int c = i - b * per_tok;
    float w0 = g_tw[b * 2 + 0];
    float w1 = g_tw[b * 2 + 1];
    float4 a = ((const float4*)(g_y + (size_t)(b * 2 + 0) * DOUT))[c];
    float4 d = ((const float4*)(g_y + (size_t)(b * 2 + 1) * DOUT))[c];
    float4 r;
    r.x = w0 * a.x + w1 * d.x;
    r.y = w0 * a.y + w1 * d.y;
    r.z = w0 * a.z + w1 * d.z;
    r.w = w0 * a.w + w1 * d.w;
    ((float4*)out)[i] = r;
}

// ---------------------------------------------------------------------------
extern "C" void kernel_launch(void* const* d_in, const int* in_sizes, int n_in,
                              void* d_out, int out_size) {
    const float* x  = (const float*)d_in[0];
    const float* gw = (const float*)d_in[1];
    const float* w1 = (const float*)d_in[2];
    const float* b1 = (const float*)d_in[3];
    const float* w2 = (const float*)d_in[4];
    const float* b2 = (const float*)d_in[5];
    float* out = (float*)d_out;

    init_kernel<<<1, 32>>>();
    gate_kernel<<<NTOK, 128>>>(x, gw);

    // phase 1: h = relu(x @ w1^T + b1), grouped by expert
    moe_gemm<DIN, DHID, true>
        <<<dim3(CAP / 128, DHID / 128, NEXP), 256>>>(x, w1, b1);

    // phase 2: y = h @ w2^T + b2
    moe_gemm<DHID, DOUT, false>
        <<<dim3(CAP / 128, DOUT / 128, NEXP), 256>>>(x, w2, b2);

    combine_kernel<<<(NTOK * DOUT / 4 + 255) / 256, 256>>>(out);
}

// round 7
// speedup vs baseline: 1.7164x; 1.7164x over previous
#include <cuda_runtime.h>
#include <cuda_bf16.h>
#include <cstdint>

// Problem constants (MoE_TopK: E=16, K=2, B=4096, D_IN=1024, D_HID=2048, D_OUT=1024)
#define NTOK  4096
#define NEXP  16
#define DIN   1024
#define DHID  2048
#define DOUT  1024
#define CAP   4096   // worst-case tokens per expert

// Scratch (no allocations allowed -> __device__ globals)
__device__ int   g_cnt[NEXP];
__device__ int   g_tok[NEXP * CAP];
__device__ int   g_slot[NEXP * CAP];
__device__ float g_tw[NTOK * 2];
__device__ float g_h[NTOK * 2 * DHID];   // 64 MB
__device__ float g_y[NTOK * 2 * DOUT];   // 32 MB

// ---------------------------------------------------------------------------
// helpers (base sm_103 ISA only: ldmatrix + mma.sync, NO tcgen05)
// ---------------------------------------------------------------------------
__device__ __forceinline__ uint32_t smem_u32(const void* p) {
    uint32_t a;
    asm("{ .reg .u64 t; cvta.to.shared.u64 t, %1; cvt.u32.u64 %0, t; }"
        : "=r"(a) : "l"(p));
    return a;
}

__device__ __forceinline__ void ldsm4(uint32_t* r, uint32_t addr) {
    asm volatile("ldmatrix.sync.aligned.m8n8.x4.shared.b16 {%0,%1,%2,%3}, [%4];"
                 : "=r"(r[0]), "=r"(r[1]), "=r"(r[2]), "=r"(r[3]) : "r"(addr));
}

__device__ __forceinline__ void mma_bf16(float* c, const uint32_t* a,
                                         uint32_t b0, uint32_t b1) {
    asm volatile("mma.sync.aligned.m16n8k16.row.col.f32.bf16.bf16.f32 "
                 "{%0,%1,%2,%3}, {%4,%5,%6,%7}, {%8,%9}, {%0,%1,%2,%3};"
                 : "+f"(c[0]), "+f"(c[1]), "+f"(c[2]), "+f"(c[3])
                 : "r"(a[0]), "r"(a[1]), "r"(a[2]), "r"(a[3]), "r"(b0), "r"(b1));
}

// ---------------------------------------------------------------------------
// 0) zero per-expert counters (graph replays)
// ---------------------------------------------------------------------------
__global__ void init_kernel() {
    if (threadIdx.x < NEXP) g_cnt[threadIdx.x] = 0;
}

// ---------------------------------------------------------------------------
// 1) gating: scores = x @ gate_w^T, top-2, softmax over 2, route
// ---------------------------------------------------------------------------
__global__ __launch_bounds__(128)
void gate_kernel(const float* __restrict__ x, const float* __restrict__ gw) {
    __shared__ float xs[DIN];
    __shared__ float sc[NEXP];

    const int b = blockIdx.x;
    const float4* xg  = (const float4*)(x + (size_t)b * DIN);
    float4*       xs4 = (float4*)xs;
    for (int i = threadIdx.x; i < DIN / 4; i += blockDim.x) xs4[i] = xg[i];
    __syncthreads();

    const int warp = threadIdx.x >> 5;
    const int lane = threadIdx.x & 31;
    for (int e = warp; e < NEXP; e += 4) {
        const float* w = gw + (size_t)e * DIN;
        float s = 0.f;
        for (int i = lane; i < DIN; i += 32) s += xs[i] * __ldg(&w[i]);
        #pragma unroll
        for (int o = 16; o > 0; o >>= 1) s += __shfl_xor_sync(0xffffffffu, s, o);
        if (lane == 0) sc[e] = s;
    }
    __syncthreads();

    if (threadIdx.x == 0) {
        int i0 = 0; float v0 = sc[0];
        #pragma unroll
        for (int e = 1; e < NEXP; e++) if (sc[e] > v0) { v0 = sc[e]; i0 = e; }
        int i1 = -1; float v1 = -3.4e38f;
        #pragma unroll
        for (int e = 0; e < NEXP; e++)
            if (e != i0 && sc[e] > v1) { v1 = sc[e]; i1 = e; }

        float e1  = __expf(v1 - v0);
        float inv = 1.f / (1.f + e1);
        g_tw[b * 2 + 0] = inv;
        g_tw[b * 2 + 1] = e1 * inv;

        int p0 = atomicAdd(&g_cnt[i0], 1);
        g_tok[i0 * CAP + p0]  = b;
        g_slot[i0 * CAP + p0] = 0;
        int p1 = atomicAdd(&g_cnt[i1], 1);
        g_tok[i1 * CAP + p1]  = b;
        g_slot[i1 * CAP + p1] = 1;
    }
}

// ---------------------------------------------------------------------------
// 2)+3) grouped HMMA (mma.sync bf16) GEMM over gathered rows, 3-pass split.
//    CTA tile M=128 x N=128, K-chunk 64. 8 warps (4x2) of 32x64 warp tiles.
//    smem stage = {A_hi, A_lo, B_hi, B_lo}, 128 rows x 64 bf16 each (swizzled),
//    double buffered.
// ---------------------------------------------------------------------------
#define TILE_BYTES  16384                 // 128 rows * 128 B
#define STAGE_BYTES (4 * TILE_BYTES)      // 64 KB
#define DSMEM_BYTES (2 * STAGE_BYTES)     // 128 KB

template<int KDIM, int NDIM, bool PHASE1>
__global__ __launch_bounds__(256)
void moe_gemm_mma(const float* __restrict__ Ax,     // x (phase1) / unused (phase2)
                  const float* __restrict__ W,      // [NEXP, NDIM, KDIM]
                  const float* __restrict__ bias)   // [NEXP, NDIM]
{
    extern __shared__ char dsm[];
    __shared__ int srow[128];
    __shared__ int scrow[128];

    const int e   = blockIdx.z;
    const int n_e = g_cnt[e];
    const int m0  = blockIdx.x * 128;
    if (m0 >= n_e) return;                          // dead tile
    const int n0  = blockIdx.y * 128;

    const float* A  = PHASE1 ? Ax : g_h;
    float*       C  = PHASE1 ? g_h : g_y;
    const float* Wb = W + (size_t)e * NDIM * KDIM;

    const int tid = threadIdx.x;
    if (tid < 128) {
        int p = m0 + tid;
        if (p < n_e) {
            int tok  = g_tok[e * CAP + p];
            int slot = g_slot[e * CAP + p];
            srow[tid]  = PHASE1 ? tok : (tok * 2 + slot);
            scrow[tid] = tok * 2 + slot;
        } else { srow[tid] = -1; scrow[tid] = -1; }
    }
    __syncthreads();

    const int w   = tid >> 5;
    const int t   = tid & 31;
    const int m0w = (w & 3) * 32;    // warp M offset in CTA tile
    const int n0w = (w >> 2) * 64;   // warp N offset
    const int s7  = t & 7;

    const uint32_t sbase = smem_u32(dsm);

    // per-lane ldmatrix row offsets (bytes), fixed across k-steps
    int arow[2], brow[4];
    #pragma unroll
    for (int mi = 0; mi < 2; mi++)
        arow[mi] = (m0w + 16 * mi + ((t >> 3) & 1) * 8 + s7) * 128;
    #pragma unroll
    for (int p = 0; p < 4; p++)
        brow[p] = (n0w + 16 * p + ((t >> 4) & 1) * 8 + s7) * 128;
    const int ahi = t >> 4;          // A k-col select bit
    const int bhi = (t >> 3) & 1;    // B k-col select bit

    float acc[2][8][4];
    #pragma unroll
    for (int mi = 0; mi < 2; mi++)
        #pragma unroll
        for (int nf = 0; nf < 8; nf++)
            #pragma unroll
            for (int j = 0; j < 4; j++) acc[mi][nf][j] = 0.f;

    // ---- loader: 256 rows (A:0-127 gathered, B:128-255 weights) x 64 k ----
    float4 buf[16];
    auto ldg_chunk = [&](int k0) {
        #pragma unroll
        for (int i = 0; i < 16; i++) {
            int f   = tid + i * 256;          // 0..4095 float4 slots
            int row = f >> 4;                 // 0..255
            int kq  = (f & 15) << 2;          // 0..60
            if (row < 128) {
                int ar = srow[row];
                buf[i] = (ar >= 0)
                    ? *(const float4*)(A + (size_t)ar * KDIM + k0 + kq)
                    : make_float4(0.f, 0.f, 0.f, 0.f);
            } else {
                buf[i] = *(const float4*)(Wb + (size_t)(n0 + row - 128) * KDIM + k0 + kq);
            }
        }
    };
    auto sts_chunk = [&](int stage) {
        char* sb = dsm + stage * STAGE_BYTES;
        #pragma unroll
        for (int i = 0; i < 16; i++) {
            int f   = tid + i * 256;
            int row = f >> 4;
            int kq  = (f & 15) << 2;
            int rr  = row & 127;
            float4 v = buf[i];
            __nv_bfloat162 h01 = __floats2bfloat162_rn(v.x, v.y);
            __nv_bfloat162 h23 = __floats2bfloat162_rn(v.z, v.w);
            float2 f01 = __bfloat1622float2(h01);
            float2 f23 = __bfloat1622float2(h23);
            __nv_bfloat162 l01 = __floats2bfloat162_rn(v.x - f01.x, v.y - f01.y);
            __nv_bfloat162 l23 = __floats2bfloat162_rn(v.z - f23.x, v.w - f23.y);
            uint2 hv, lv;
            hv.x = *(uint32_t*)&h01; hv.y = *(uint32_t*)&h23;
            lv.x = *(uint32_t*)&l01; lv.y = *(uint32_t*)&l23;
            uint32_t off = (uint32_t)rr * 128u + (uint32_t)kq * 2u;
            uint32_t sw  = off ^ ((off >> 3) & 0x70u);
            int th = (row < 128) ? 0 : (2 * TILE_BYTES);   // Ah or Bh
            *(uint2*)(sb + th + sw)              = hv;
            *(uint2*)(sb + th + TILE_BYTES + sw) = lv;
        }
    };

    constexpr int NC = KDIM / 64;

    ldg_chunk(0);
    sts_chunk(0);
    __syncthreads();

    for (int c = 0; c < NC; c++) {
        if (c + 1 < NC) ldg_chunk((c + 1) * 64);   // prefetch overlaps mma

        const uint32_t st  = sbase + (c & 1) * STAGE_BYTES;
        const uint32_t sAh = st;
        const uint32_t sAl = st + TILE_BYTES;
        const uint32_t sBh = st + 2 * TILE_BYTES;
        const uint32_t sBl = st + 3 * TILE_BYTES;

        #pragma unroll
        for (int ks = 0; ks < 4; ks++) {
            const uint32_t kxa = (uint32_t)(((2 * ks + ahi) ^ s7) << 4);
            const uint32_t kxb = (uint32_t)(((2 * ks + bhi) ^ s7) << 4);
            uint32_t Ah[2][4], Al[2][4];
            ldsm4(Ah[0], sAh + arow[0] + kxa);
            ldsm4(Ah[1], sAh + arow[1] + kxa);
            ldsm4(Al[0], sAl + arow[0] + kxa);
            ldsm4(Al[1], sAl + arow[1] + kxa);
            #pragma unroll
            for (int p = 0; p < 4; p++) {
                uint32_t Bh[4], Bl[4];
                ldsm4(Bh, sBh + brow[p] + kxb);
                ldsm4(Bl, sBl + brow[p] + kxb);
                #pragma unroll
                for (int j = 0; j < 2; j++) {
                    const int nf = 2 * p + j;
                    #pragma unroll
                    for (int mi = 0; mi < 2; mi++) {
                        mma_bf16(acc[mi][nf], Ah[mi], Bh[2 * j], Bh[2 * j + 1]);
                        mma_bf16(acc[mi][nf], Ah[mi], Bl[2 * j], Bl[2 * j + 1]);
                        mma_bf16(acc[mi][nf], Al[mi], Bh[2 * j], Bh[2 * j + 1]);
                    }
                }
            }
        }

        if (c + 1 < NC) sts_chunk((c + 1) & 1);
        __syncthreads();
    }

    // ---- epilogue: bias (+relu phase1), scatter rows via scrow ----
    const int trow = t >> 2;          // 0..7
    const int tcol = (t & 3) * 2;     // 0,2,4,6
    float2 bb[8];
    #pragma unroll
    for (int nf = 0; nf < 8; nf++)
        bb[nf] = *(const float2*)(bias + (size_t)e * NDIM + n0 + n0w + nf * 8 + tcol);

    #pragma unroll
    for (int mi = 0; mi < 2; mi++) {
        const int ml  = m0w + 16 * mi + trow;
        const int cr0 = scrow[ml];
        const int cr1 = scrow[ml + 8];
        #pragma unroll
        for (int nf = 0; nf < 8; nf++) {
            const int col = n0 + n0w + nf * 8 + tcol;
            float* a = acc[mi][nf];
            if (cr0 >= 0) {
                float vx = a[0] + bb[nf].x, vy = a[1] + bb[nf].y;
                if (PHASE1) { vx = fmaxf(vx, 0.f); vy = fmaxf(vy, 0.f); }
                *(float2*)(C + (size_t)cr0 * NDIM + col) = make_float2(vx, vy);
            }
            if (cr1 >= 0) {
                float vx = a[2] + bb[nf].x, vy = a[3] + bb[nf].y;
                if (PHASE1) { vx = fmaxf(vx, 0.f); vy = fmaxf(vy, 0.f); }
                *(float2*)(C + (size_t)cr1 * NDIM + col) = make_float2(vx, vy);
            }
        }
    }
}

// ---------------------------------------------------------------------------
// 4) combine: out[b] = w0*y[b,0] + w1*y[b,1]
// ---------------------------------------------------------------------------
__global__ __launch_bounds__(256)
void combine_kernel(float* __restrict__ out) {
    int i = blockIdx.x * blockDim.x + threadIdx.x;   // float4 index
    const int per_tok = DOUT / 4;
    if (i >= NTOK * per_tok) return;
    int b = i / per_tok;
    int c = i - b * per_tok;
    float w0 = g_tw[b * 2 + 0];
    float w1 = g_tw[b * 2 + 1];
    float4 a = ((const float4*)(g_y + (size_t)(b * 2 + 0) * DOUT))[c];
    float4 d = ((const float4*)(g_y + (size_t)(b * 2 + 1) * DOUT))[c];
    float4 r;
    r.x = w0 * a.x + w1 * d.x;
    r.y = w0 * a.y + w1 * d.y;
    r.z = w0 * a.z + w1 * d.z;
    r.w = w0 * a.w + w1 * d.w;
    ((float4*)out)[i] = r;
}

// ---------------------------------------------------------------------------
extern "C" void kernel_launch(void* const* d_in, const int* in_sizes, int n_in,
                              void* d_out, int out_size) {
    const float* x  = (const float*)d_in[0];
    const float* gw = (const float*)d_in[1];
    const float* w1 = (const float*)d_in[2];
    const float* b1 = (const float*)d_in[3];
    const float* w2 = (const float*)d_in[4];
    const float* b2 = (const float*)d_in[5];
    float* out = (float*)d_out;

    cudaFuncSetAttribute(moe_gemm_mma<DIN, DHID, true>,
                         cudaFuncAttributeMaxDynamicSharedMemorySize, DSMEM_BYTES);
    cudaFuncSetAttribute(moe_gemm_mma<DHID, DOUT, false>,
                         cudaFuncAttributeMaxDynamicSharedMemorySize, DSMEM_BYTES);

    init_kernel<<<1, 32>>>();
    gate_kernel<<<NTOK, 128>>>(x, gw);

    // phase 1: h = relu(x @ w1^T + b1)
    moe_gemm_mma<DIN, DHID, true>
        <<<dim3(CAP / 128, DHID / 128, NEXP), 256, DSMEM_BYTES>>>(x, w1, b1);

    // phase 2: y = h @ w2^T + b2
    moe_gemm_mma<DHID, DOUT, false>
        <<<dim3(CAP / 128, DOUT / 128, NEXP), 256, DSMEM_BYTES>>>(x, w2, b2);

    combine_kernel<<<(NTOK * DOUT / 4 + 255) / 256, 256>>>(out);
}

// round 8
// speedup vs baseline: 2.8483x; 1.6595x over previous
#include <cuda_runtime.h>
#include <cuda_bf16.h>
#include <cstdint>

// Problem constants (MoE_TopK: E=16, K=2, B=4096, D_IN=1024, D_HID=2048, D_OUT=1024)
#define NTOK  4096
#define NEXP  16
#define DIN   1024
#define DHID  2048
#define DOUT  1024
#define CAP   4096   // worst-case tokens per expert

// Scratch (no allocations allowed -> __device__ globals)
__device__ int   g_cnt[NEXP];
__device__ int   g_tok[NEXP * CAP];
__device__ int   g_slot[NEXP * CAP];
__device__ float g_tw[NTOK * 2];
__device__ float g_y[NTOK * 2 * DOUT];                 // 32 MB

// split (hi/lo bf16) operands
__device__ __nv_bfloat16 g_xh[NTOK * DIN];             // 8 MB
__device__ __nv_bfloat16 g_xl[NTOK * DIN];
__device__ __nv_bfloat16 g_w1h[NEXP * DHID * DIN];     // 64 MB
__device__ __nv_bfloat16 g_w1l[NEXP * DHID * DIN];
__device__ __nv_bfloat16 g_w2h[NEXP * DOUT * DHID];    // 64 MB
__device__ __nv_bfloat16 g_w2l[NEXP * DOUT * DHID];
__device__ __nv_bfloat16 g_hh[NTOK * 2 * DHID];        // 32 MB
__device__ __nv_bfloat16 g_hl[NTOK * 2 * DHID];

// ---------------------------------------------------------------------------
// helpers (base sm_103 ISA only: ldmatrix + mma.sync + cp.async)
// ---------------------------------------------------------------------------
__device__ __forceinline__ uint32_t smem_u32(const void* p) {
    uint32_t a;
    asm("{ .reg .u64 t; cvta.to.shared.u64 t, %1; cvt.u32.u64 %0, t; }"
        : "=r"(a) : "l"(p));
    return a;
}

__device__ __forceinline__ void ldsm4(uint32_t* r, uint32_t addr) {
    asm volatile("ldmatrix.sync.aligned.m8n8.x4.shared.b16 {%0,%1,%2,%3}, [%4];"
                 : "=r"(r[0]), "=r"(r[1]), "=r"(r[2]), "=r"(r[3]) : "r"(addr));
}

__device__ __forceinline__ void mma_bf16(float* c, const uint32_t* a,
                                         uint32_t b0, uint32_t b1) {
    asm volatile("mma.sync.aligned.m16n8k16.row.col.f32.bf16.bf16.f32 "
                 "{%0,%1,%2,%3}, {%4,%5,%6,%7}, {%8,%9}, {%0,%1,%2,%3};"
                 : "+f"(c[0]), "+f"(c[1]), "+f"(c[2]), "+f"(c[3])
                 : "r"(a[0]), "r"(a[1]), "r"(a[2]), "r"(a[3]), "r"(b0), "r"(b1));
}

__device__ __forceinline__ void cp16(uint32_t dst, const void* src, int src_bytes) {
    asm volatile("cp.async.cg.shared.global [%0], [%1], 16, %2;"
                 :: "r"(dst), "l"(src), "r"(src_bytes));
}
__device__ __forceinline__ void cp_commit() {
    asm volatile("cp.async.commit_group;");
}
template<int N>
__device__ __forceinline__ void cp_wait() {
    asm volatile("cp.async.wait_group %0;" :: "n"(N));
}

__device__ __forceinline__ void split2(float x, float y,
                                       uint32_t& hv, uint32_t& lv) {
    __nv_bfloat162 h = __floats2bfloat162_rn(x, y);
    float2 hf = __bfloat1622float2(h);
    __nv_bfloat162 l = __floats2bfloat162_rn(x - hf.x, y - hf.y);
    hv = *(uint32_t*)&h;
    lv = *(uint32_t*)&l;
}

// ---------------------------------------------------------------------------
// 0) zero per-expert counters (graph replays)
// ---------------------------------------------------------------------------
__global__ void init_kernel() {
    if (threadIdx.x < NEXP) g_cnt[threadIdx.x] = 0;
}

// ---------------------------------------------------------------------------
// 0b) split fp32 -> bf16 hi/lo (for w1, w2)
// ---------------------------------------------------------------------------
__global__ __launch_bounds__(256)
void split_kernel(const float* __restrict__ src,
                  __nv_bfloat16* __restrict__ hi,
                  __nv_bfloat16* __restrict__ lo, int n4) {
    int i = blockIdx.x * blockDim.x + threadIdx.x;
    int stride = gridDim.x * blockDim.x;
    for (; i < n4; i += stride) {
        float4 v = ((const float4*)src)[i];
        uint2 hv, lv;
        split2(v.x, v.y, hv.x, lv.x);
        split2(v.z, v.w, hv.y, lv.y);
        ((uint2*)hi)[i] = hv;
        ((uint2*)lo)[i] = lv;
    }
}

// ---------------------------------------------------------------------------
// 1) gating: scores = x @ gate_w^T, top-2, softmax over 2, route.
//    Also writes the hi/lo bf16 split of x (row already in smem).
// ---------------------------------------------------------------------------
__global__ __launch_bounds__(128)
void gate_kernel(const float* __restrict__ x, const float* __restrict__ gw) {
    __shared__ float xs[DIN];
    __shared__ float sc[NEXP];

    const int b = blockIdx.x;
    const float4* xg  = (const float4*)(x + (size_t)b * DIN);
    float4*       xs4 = (float4*)xs;
    for (int i = threadIdx.x; i < DIN / 4; i += blockDim.x) xs4[i] = xg[i];
    __syncthreads();

    // split x row -> g_xh / g_xl
    for (int i = threadIdx.x; i < DIN / 4; i += blockDim.x) {
        float4 v = xs4[i];
        uint2 hv, lv;
        split2(v.x, v.y, hv.x, lv.x);
        split2(v.z, v.w, hv.y, lv.y);
        ((uint2*)(g_xh + (size_t)b * DIN))[i] = hv;
        ((uint2*)(g_xl + (size_t)b * DIN))[i] = lv;
    }

    const int warp = threadIdx.x >> 5;
    const int lane = threadIdx.x & 31;
    for (int e = warp; e < NEXP; e += 4) {
        const float* w = gw + (size_t)e * DIN;
        float s = 0.f;
        for (int i = lane; i < DIN; i += 32) s += xs[i] * __ldg(&w[i]);
        #pragma unroll
        for (int o = 16; o > 0; o >>= 1) s += __shfl_xor_sync(0xffffffffu, s, o);
        if (lane == 0) sc[e] = s;
    }
    __syncthreads();

    if (threadIdx.x == 0) {
        int i0 = 0; float v0 = sc[0];
        #pragma unroll
        for (int e = 1; e < NEXP; e++) if (sc[e] > v0) { v0 = sc[e]; i0 = e; }
        int i1 = -1; float v1 = -3.4e38f;
        #pragma unroll
        for (int e = 0; e < NEXP; e++)
            if (e != i0 && sc[e] > v1) { v1 = sc[e]; i1 = e; }

        float e1  = __expf(v1 - v0);
        float inv = 1.f / (1.f + e1);
        g_tw[b * 2 + 0] = inv;
        g_tw[b * 2 + 1] = e1 * inv;

        int p0 = atomicAdd(&g_cnt[i0], 1);
        g_tok[i0 * CAP + p0]  = b;
        g_slot[i0 * CAP + p0] = 0;
        int p1 = atomicAdd(&g_cnt[i1], 1);
        g_tok[i1 * CAP + p1]  = b;
        g_slot[i1 * CAP + p1] = 1;
    }
}

// ---------------------------------------------------------------------------
// 2)+3) grouped HMMA GEMM, preconverted bf16 hi/lo, cp.async 3-stage pipeline.
//    CTA tile 128x128, K-chunk 32. Stage = A(hi|lo) 16KB + B(hi|lo) 16KB.
//    Row layout: 128B = [hi k0..31 | lo k0..31], swizzle off^((off>>3)&0x70).
// ---------------------------------------------------------------------------
#define KC          32
#define TILE_BYTES  16384                 // 128 rows * 128 B
#define STAGE_BYTES (2 * TILE_BYTES)      // 32 KB
#define NSTAGE      3
#define DSMEM_BYTES (NSTAGE * STAGE_BYTES) // 96 KB

template<int KDIM, int NDIM, bool PHASE1>
__global__ __launch_bounds__(256, 2)
void moe_gemm_cp(const __nv_bfloat16* __restrict__ Ah_g,
                 const __nv_bfloat16* __restrict__ Al_g,
                 const __nv_bfloat16* __restrict__ Wh_g,
                 const __nv_bfloat16* __restrict__ Wl_g,
                 const float* __restrict__ bias)
{
    extern __shared__ char dsm[];
    __shared__ int srow[128];
    __shared__ int scrow[128];

    const int e   = blockIdx.z;
    const int n_e = g_cnt[e];
    const int m0  = blockIdx.x * 128;
    if (m0 >= n_e) return;                          // dead tile
    const int n0  = blockIdx.y * 128;

    const __nv_bfloat16* Wbh = Wh_g + (size_t)e * NDIM * KDIM;
    const __nv_bfloat16* Wbl = Wl_g + (size_t)e * NDIM * KDIM;

    const int tid = threadIdx.x;
    if (tid < 128) {
        int p = m0 + tid;
        if (p < n_e) {
            int tok  = g_tok[e * CAP + p];
            int slot = g_slot[e * CAP + p];
            srow[tid]  = PHASE1 ? tok : (tok * 2 + slot);
            scrow[tid] = tok * 2 + slot;
        } else { srow[tid] = -1; scrow[tid] = -1; }
    }
    __syncthreads();

    const uint32_t sbase = smem_u32(dsm);

    // ---- loader: one K-chunk (32 k) for A(128 rows) + B(128 rows), hi+lo ----
    auto load_stage = [&](int s, int k0) {
        const uint32_t stb = sbase + s * STAGE_BYTES;
        #pragma unroll
        for (int i = 0; i < 8; i++) {
            int f    = tid + i * 256;          // 0..2047 16B-chunks
            int tile = f >> 10;                // 0: A, 1: B
            int rr   = (f >> 3) & 127;
            int u    = f & 7;                  // col unit: 0-3 hi, 4-7 lo
            int half = u >> 2;
            int ko   = (u & 3) * 8;            // bf16 offset within 32-k chunk
            const __nv_bfloat16* src;
            int sz = 16;
            if (tile == 0) {
                int ar = srow[rr];
                if (ar < 0) { ar = 0; sz = 0; }
                src = (half ? Al_g : Ah_g) + (size_t)ar * KDIM + k0 + ko;
            } else {
                src = (half ? Wbl : Wbh) + (size_t)(n0 + rr) * KDIM + k0 + ko;
            }
            uint32_t off = (uint32_t)rr * 128u + (uint32_t)u * 16u;
            uint32_t sw  = off ^ ((off >> 3) & 0x70u);
            cp16(stb + tile * TILE_BYTES + sw, src, sz);
        }
        cp_commit();
    };

    const int w   = tid >> 5;
    const int t   = tid & 31;
    const int m0w = (w & 3) * 32;    // warp M offset
    const int n0w = (w >> 2) * 64;   // warp N offset
    const int s7  = t & 7;

    int arow[2], brow[4];
    #pragma unroll
    for (int mi = 0; mi < 2; mi++)
        arow[mi] = (m0w + 16 * mi + ((t >> 3) & 1) * 8 + s7) * 128;
    #pragma unroll
    for (int p = 0; p < 4; p++)
        brow[p] = (n0w + 16 * p + ((t >> 4) & 1) * 8 + s7) * 128;
    const int ahi = t >> 4;
    const int bhi = (t >> 3) & 1;

    float acc[2][8][4];
    #pragma unroll
    for (int mi = 0; mi < 2; mi++)
        #pragma unroll
        for (int nf = 0; nf < 8; nf++)
            #pragma unroll
            for (int j = 0; j < 4; j++) acc[mi][nf][j] = 0.f;

    constexpr int NC = KDIM / KC;

    load_stage(0, 0);
    load_stage(1, KC);

    int slot = 0;
    for (int c = 0; c < NC; c++) {
        if (c == NC - 1) cp_wait<0>(); else cp_wait<1>();
        __syncthreads();

        if (c + 2 < NC) {
            int ns = slot + 2; if (ns >= NSTAGE) ns -= NSTAGE;
            load_stage(ns, (c + 2) * KC);
        }

        const uint32_t stb = sbase + slot * STAGE_BYTES;
        const uint32_t sA  = stb;
        const uint32_t sB  = stb + TILE_BYTES;

        #pragma unroll
        for (int ks = 0; ks < 2; ks++) {
            const uint32_t kah = (uint32_t)(((2 * ks + ahi) ^ s7) << 4);
            const uint32_t kal = (uint32_t)(((4 + 2 * ks + ahi) ^ s7) << 4);
            const uint32_t kbh = (uint32_t)(((2 * ks + bhi) ^ s7) << 4);
            const uint32_t kbl = (uint32_t)(((4 + 2 * ks + bhi) ^ s7) << 4);
            uint32_t Ah[2][4], Al[2][4];
            ldsm4(Ah[0], sA + arow[0] + kah);
            ldsm4(Ah[1], sA + arow[1] + kah);
            ldsm4(Al[0], sA + arow[0] + kal);
            ldsm4(Al[1], sA + arow[1] + kal);
            #pragma unroll
            for (int p = 0; p < 4; p++) {
                uint32_t Bh[4], Bl[4];
                ldsm4(Bh, sB + brow[p] + kbh);
                ldsm4(Bl, sB + brow[p] + kbl);
                #pragma unroll
                for (int j = 0; j < 2; j++) {
                    const int nf = 2 * p + j;
                    #pragma unroll
                    for (int mi = 0; mi < 2; mi++) {
                        mma_bf16(acc[mi][nf], Ah[mi], Bh[2 * j], Bh[2 * j + 1]);
                        mma_bf16(acc[mi][nf], Ah[mi], Bl[2 * j], Bl[2 * j + 1]);
                        mma_bf16(acc[mi][nf], Al[mi], Bh[2 * j], Bh[2 * j + 1]);
                    }
                }
            }
        }
        if (++slot == NSTAGE) slot = 0;
    }

    // ---- epilogue ----
    const int trow = t >> 2;          // 0..7
    const int tcol = (t & 3) * 2;     // 0,2,4,6
    float2 bb[8];
    #pragma unroll
    for (int nf = 0; nf < 8; nf++)
        bb[nf] = *(const float2*)(bias + (size_t)e * NDIM + n0 + n0w + nf * 8 + tcol);

    #pragma unroll
    for (int mi = 0; mi < 2; mi++) {
        const int ml  = m0w + 16 * mi + trow;
        const int cr0 = scrow[ml];
        const int cr1 = scrow[ml + 8];
        #pragma unroll
        for (int nf = 0; nf < 8; nf++) {
            const int col = n0 + n0w + nf * 8 + tcol;
            float* a = acc[mi][nf];
            #pragma unroll
            for (int h = 0; h < 2; h++) {
                const int cr = h ? cr1 : cr0;
                if (cr < 0) continue;
                float vx = a[2 * h + 0] + bb[nf].x;
                float vy = a[2 * h + 1] + bb[nf].y;
                if (PHASE1) {
                    vx = fmaxf(vx, 0.f); vy = fmaxf(vy, 0.f);
                    uint32_t hv, lv;
                    split2(vx, vy, hv, lv);
                    *(uint32_t*)(g_hh + (size_t)cr * DHID + col) = hv;
                    *(uint32_t*)(g_hl + (size_t)cr * DHID + col) = lv;
                } else {
                    *(float2*)(g_y + (size_t)cr * NDIM + col) = make_float2(vx, vy);
                }
            }
        }
    }
}

// ---------------------------------------------------------------------------
// 4) combine: out[b] = w0*y[b,0] + w1*y[b,1]
// ---------------------------------------------------------------------------
__global__ __launch_bounds__(256)
void combine_kernel(float* __restrict__ out) {
    int i = blockIdx.x * blockDim.x + threadIdx.x;   // float4 index
    const int per_tok = DOUT / 4;
    if (i >= NTOK * per_tok) return;
    int b = i / per_tok;
    int c = i - b * per_tok;
    float w0 = g_tw[b * 2 + 0];
    float w1 = g_tw[b * 2 + 1];
    float4 a = ((const float4*)(g_y + (size_t)(b * 2 + 0) * DOUT))[c];
    float4 d = ((const float4*)(g_y + (size_t)(b * 2 + 1) * DOUT))[c];
    float4 r;
    r.x = w0 * a.x + w1 * d.x;
    r.y = w0 * a.y + w1 * d.y;
    r.z = w0 * a.z + w1 * d.z;
    r.w = w0 * a.w + w1 * d.w;
    ((float4*)out)[i] = r;
}

// ---------------------------------------------------------------------------
extern "C" void kernel_launch(void* const* d_in, const int* in_sizes, int n_in,
                              void* d_out, int out_size) {
    const float* x  = (const float*)d_in[0];
    const float* gw = (const float*)d_in[1];
    const float* w1 = (const float*)d_in[2];
    const float* b1 = (const float*)d_in[3];
    const float* w2 = (const float*)d_in[4];
    const float* b2 = (const float*)d_in[5];
    float* out = (float*)d_out;

    cudaFuncSetAttribute(moe_gemm_cp<DIN, DHID, true>,
                         cudaFuncAttributeMaxDynamicSharedMemorySize, DSMEM_BYTES);
    cudaFuncSetAttribute(moe_gemm_cp<DHID, DOUT, false>,
                         cudaFuncAttributeMaxDynamicSharedMemorySize, DSMEM_BYTES);

    __nv_bfloat16 *w1h, *w1l, *w2h, *w2l, *xh, *xl;
    cudaGetSymbolAddress((void**)&w1h, g_w1h);
    cudaGetSymbolAddress((void**)&w1l, g_w1l);
    cudaGetSymbolAddress((void**)&w2h, g_w2h);
    cudaGetSymbolAddress((void**)&w2l, g_w2l);
    cudaGetSymbolAddress((void**)&xh,  g_xh);
    cudaGetSymbolAddress((void**)&xl,  g_xl);
    __nv_bfloat16 *hh, *hl;
    cudaGetSymbolAddress((void**)&hh, g_hh);
    cudaGetSymbolAddress((void**)&hl, g_hl);

    init_kernel<<<1, 32>>>();
    gate_kernel<<<NTOK, 128>>>(x, gw);

    // split weights to bf16 hi/lo
    split_kernel<<<8192, 256>>>(w1, w1h, w1l, NEXP * DHID * DIN / 4);
    split_kernel<<<8192, 256>>>(w2, w2h, w2l, NEXP * DOUT * DHID / 4);

    // phase 1: h = relu(x @ w1^T + b1)  (A = split x)
    moe_gemm_cp<DIN, DHID, true>
        <<<dim3(CAP / 128, DHID / 128, NEXP), 256, DSMEM_BYTES>>>(xh, xl, w1h, w1l, b1);

    // phase 2: y = h @ w2^T + b2  (A = split h)
    moe_gemm_cp<DHID, DOUT, false>
        <<<dim3(CAP / 128, DOUT / 128, NEXP), 256, DSMEM_BYTES>>>(hh, hl, w2h, w2l, b2);

    combine_kernel<<<(NTOK * DOUT / 4 + 255) / 256, 256>>>(out);
}

// round 12
// speedup vs baseline: 3.4707x; 1.2185x over previous
#include <cuda_runtime.h>
#include <cuda_bf16.h>
#include <cstdint>

// Problem constants (MoE_TopK: E=16, K=2, B=4096, D_IN=1024, D_HID=2048, D_OUT=1024)
#define NTOK  4096
#define NEXP  16
#define DIN   1024
#define DHID  2048
#define DOUT  1024
#define CAP   4096   // worst-case tokens per expert

// Scratch (no allocations allowed -> __device__ globals)
__device__ int   g_cnt[NEXP];
__device__ int   g_tok[NEXP * CAP];
__device__ int   g_slot[NEXP * CAP];
__device__ float g_tw[NTOK * 2];
__device__ float g_h[NTOK * 2 * DHID];   // 64 MB fp32 hidden
__device__ float g_y[NTOK * 2 * DOUT];   // 32 MB

// ---------------------------------------------------------------------------
// helpers (base sm_103 ISA: mma.sync tf32 + cp.async; NO tcgen05, NO ldmatrix)
// ---------------------------------------------------------------------------
__device__ __forceinline__ uint32_t smem_u32(const void* p) {
    uint32_t a;
    asm("{ .reg .u64 t; cvta.to.shared.u64 t, %1; cvt.u32.u64 %0, t; }"
        : "=r"(a) : "l"(p));
    return a;
}

// shared load + round-to-nearest tf32 conversion (unbiased; raw truncation
// would add a coherent ~5e-4 bias over K=1024/2048 dots)
__device__ __forceinline__ uint32_t lds_tf32(uint32_t addr) {
    uint32_t v;
    asm volatile("{ .reg .b32 t; ld.shared.b32 t, [%1]; cvt.rna.tf32.f32 %0, t; }"
                 : "=r"(v) : "r"(addr));
    return v;
}

__device__ __forceinline__ void mma_tf32(float* c, const uint32_t* a,
                                         uint32_t b0, uint32_t b1) {
    asm volatile("mma.sync.aligned.m16n8k8.row.col.f32.tf32.tf32.f32 "
                 "{%0,%1,%2,%3}, {%4,%5,%6,%7}, {%8,%9}, {%0,%1,%2,%3};"
                 : "+f"(c[0]), "+f"(c[1]), "+f"(c[2]), "+f"(c[3])
                 : "r"(a[0]), "r"(a[1]), "r"(a[2]), "r"(a[3]), "r"(b0), "r"(b1));
}

__device__ __forceinline__ void cp16(uint32_t dst, const void* src, int src_bytes) {
    asm volatile("cp.async.cg.shared.global [%0], [%1], 16, %2;"
                 :: "r"(dst), "l"(src), "r"(src_bytes));
}
__device__ __forceinline__ void cp_commit() {
    asm volatile("cp.async.commit_group;");
}
template<int N>
__device__ __forceinline__ void cp_wait() {
    asm volatile("cp.async.wait_group %0;" :: "n"(N));
}

// ---------------------------------------------------------------------------
// 0) zero per-expert counters (graph replays)
// ---------------------------------------------------------------------------
__global__ void init_kernel() {
    if (threadIdx.x < NEXP) g_cnt[threadIdx.x] = 0;
}

// ---------------------------------------------------------------------------
// 1) gating: scores = x @ gate_w^T, top-2, softmax over 2, route
// ---------------------------------------------------------------------------
__global__ __launch_bounds__(128)
void gate_kernel(const float* __restrict__ x, const float* __restrict__ gw) {
    __shared__ float xs[DIN];
    __shared__ float sc[NEXP];

    const int b = blockIdx.x;
    const float4* xg  = (const float4*)(x + (size_t)b * DIN);
    float4*       xs4 = (float4*)xs;
    for (int i = threadIdx.x; i < DIN / 4; i += blockDim.x) xs4[i] = xg[i];
    __syncthreads();

    const int warp = threadIdx.x >> 5;
    const int lane = threadIdx.x & 31;
    for (int e = warp; e < NEXP; e += 4) {
        const float* w = gw + (size_t)e * DIN;
        float s = 0.f;
        for (int i = lane; i < DIN; i += 32) s += xs[i] * __ldg(&w[i]);
        #pragma unroll
        for (int o = 16; o > 0; o >>= 1) s += __shfl_xor_sync(0xffffffffu, s, o);
        if (lane == 0) sc[e] = s;
    }
    __syncthreads();

    if (threadIdx.x == 0) {
        int i0 = 0; float v0 = sc[0];
        #pragma unroll
        for (int e = 1; e < NEXP; e++) if (sc[e] > v0) { v0 = sc[e]; i0 = e; }
        int i1 = -1; float v1 = -3.4e38f;
        #pragma unroll
        for (int e = 0; e < NEXP; e++)
            if (e != i0 && sc[e] > v1) { v1 = sc[e]; i1 = e; }

        float e1  = __expf(v1 - v0);
        float inv = 1.f / (1.f + e1);
        g_tw[b * 2 + 0] = inv;
        g_tw[b * 2 + 1] = e1 * inv;

        int p0 = atomicAdd(&g_cnt[i0], 1);
        g_tok[i0 * CAP + p0]  = b;
        g_slot[i0 * CAP + p0] = 0;
        int p1 = atomicAdd(&g_cnt[i1], 1);
        g_tok[i1 * CAP + p1]  = b;
        g_slot[i1 * CAP + p1] = 1;
    }
}

// ---------------------------------------------------------------------------
// 2)+3) grouped tf32 HMMA GEMM, fp32 operands straight from gmem.
//    CTA tile 128x128, K-chunk 32, 3-stage cp.async pipeline, 2 CTA/SM.
//    smem tiles: 128 rows x 32 fp32, rows padded to 144 B -> the tf32
//    fragment lds pattern hits banks (4*g + tig + c) mod 32: conflict-free.
// ---------------------------------------------------------------------------
#define KC          32
#define ROW_B       144                    // 128 B data + 16 B pad
#define TILE_B      (128 * ROW_B)          // 18432
#define STAGE_BYTES (2 * TILE_B)           // 36864
#define NSTAGE      3
#define DSMEM_BYTES (NSTAGE * STAGE_BYTES) // 110592

template<int KDIM, int NDIM, bool PHASE1>
__global__ __launch_bounds__(256, 2)
void moe_gemm_tf32(const float* __restrict__ A_g,     // x (phase1) / g_h (phase2)
                   const float* __restrict__ W,       // [NEXP, NDIM, KDIM]
                   const float* __restrict__ bias)    // [NEXP, NDIM]
{
    extern __shared__ char dsm[];
    __shared__ int srow[128];
    __shared__ int scrow[128];

    const int e   = blockIdx.z;
    const int n_e = g_cnt[e];
    const int m0  = blockIdx.x * 128;
    if (m0 >= n_e) return;                          // dead tile
    const int n0  = blockIdx.y * 128;

    const float* Wb = W + (size_t)e * NDIM * KDIM;

    const int tid = threadIdx.x;
    if (tid < 128) {
        int p = m0 + tid;
        if (p < n_e) {
            int tok  = g_tok[e * CAP + p];
            int slot = g_slot[e * CAP + p];
            srow[tid]  = PHASE1 ? tok : (tok * 2 + slot);
            scrow[tid] = tok * 2 + slot;
        } else { srow[tid] = -1; scrow[tid] = -1; }
    }
    __syncthreads();

    const uint32_t sbase = smem_u32(dsm);

    // ---- loader: one K-chunk (32 fp32) for A(128 rows) + B(128 rows) ----
    auto load_stage = [&](int s, int k0) {
        const uint32_t stb = sbase + s * STAGE_BYTES;
        #pragma unroll
        for (int i = 0; i < 8; i++) {
            int f    = tid + i * 256;          // 0..2047 16B-chunks
            int tile = f >> 10;                // 0: A, 1: B
            int rr   = (f >> 3) & 127;
            int ch   = f & 7;                  // 16B chunk within row (4 floats)
            const float* src;
            int sz = 16;
            if (tile == 0) {
                int ar = srow[rr];
                if (ar < 0) { ar = 0; sz = 0; }
                src = A_g + (size_t)ar * KDIM + k0 + ch * 4;
            } else {
                src = Wb + (size_t)(n0 + rr) * KDIM + k0 + ch * 4;
            }
            cp16(stb + tile * TILE_B + rr * ROW_B + ch * 16, src, sz);
        }
        cp_commit();
    };

    const int w   = tid >> 5;
    const int t   = tid & 31;
    const int m0w = (w & 3) * 32;    // warp M offset
    const int n0w = (w >> 2) * 64;   // warp N offset
    const int g   = t >> 2;          // group id 0..7
    const int tig = t & 3;           // thread-in-group

    float acc[2][8][4];
    #pragma unroll
    for (int mi = 0; mi < 2; mi++)
        #pragma unroll
        for (int nf = 0; nf < 8; nf++)
            #pragma unroll
            for (int j = 0; j < 4; j++) acc[mi][nf][j] = 0.f;

    constexpr int NC = KDIM / KC;

    load_stage(0, 0);
    load_stage(1, KC);

    int slot = 0;
    for (int c = 0; c < NC; c++) {
        if (c == NC - 1) cp_wait<0>(); else cp_wait<1>();
        __syncthreads();

        if (c + 2 < NC) {
            int ns = slot + 2; if (ns >= NSTAGE) ns -= NSTAGE;
            load_stage(ns, (c + 2) * KC);
        }

        const uint32_t stb = sbase + slot * STAGE_BYTES;
        const uint32_t sA  = stb;
        const uint32_t sB  = stb + TILE_B;

        #pragma unroll
        for (int ks = 0; ks < 4; ks++) {
            const int kb = ks * 8;
            // A fragments (m16k8, row-major): a0:(g,tig) a1:(g+8,tig)
            //                                 a2:(g,tig+4) a3:(g+8,tig+4)
            uint32_t Af[2][4];
            #pragma unroll
            for (int mi = 0; mi < 2; mi++) {
                uint32_t r0 = sA + (uint32_t)(m0w + 16 * mi + g) * ROW_B
                                 + (uint32_t)(kb + tig) * 4u;
                Af[mi][0] = lds_tf32(r0);
                Af[mi][1] = lds_tf32(r0 + 8u * ROW_B);
                Af[mi][2] = lds_tf32(r0 + 16u);
                Af[mi][3] = lds_tf32(r0 + 8u * ROW_B + 16u);
            }
            // B fragments (k8n8, col-major == row-major [n][k]):
            //   b0:(k=tig, n=g)  b1:(k=tig+4, n=g)
            #pragma unroll
            for (int nf = 0; nf < 8; nf++) {
                uint32_t rb = sB + (uint32_t)(n0w + 8 * nf + g) * ROW_B
                                 + (uint32_t)(kb + tig) * 4u;
                uint32_t b0 = lds_tf32(rb);
                uint32_t b1 = lds_tf32(rb + 16u);
                #pragma unroll
                for (int mi = 0; mi < 2; mi++)
                    mma_tf32(acc[mi][nf], Af[mi], b0, b1);
            }
        }
        if (++slot == NSTAGE) slot = 0;
    }

    // ---- epilogue: bias (+relu phase1), scatter rows via scrow ----
    // accumulator frag: c0:(g, 2*tig) c1:(g, 2*tig+1) c2:(g+8,..) c3
    const int trow = g;
    const int tcol = tig * 2;
    float2 bb[8];
    #pragma unroll
    for (int nf = 0; nf < 8; nf++)
        bb[nf] = *(const float2*)(bias + (size_t)e * NDIM + n0 + n0w + nf * 8 + tcol);

    float* C = PHASE1 ? g_h : g_y;
    #pragma unroll
    for (int mi = 0; mi < 2; mi++) {
        const int ml  = m0w + 16 * mi + trow;
        const int cr0 = scrow[ml];
        const int cr1 = scrow[ml + 8];
        #pragma unroll
        for (int nf = 0; nf < 8; nf++) {
            const int col = n0 + n0w + nf * 8 + tcol;
            float* a = acc[mi][nf];
            #pragma unroll
            for (int h = 0; h < 2; h++) {
                const int cr = h ? cr1 : cr0;
                if (cr < 0) continue;
                float vx = a[2 * h + 0] + bb[nf].x;
                float vy = a[2 * h + 1] + bb[nf].y;
                if (PHASE1) { vx = fmaxf(vx, 0.f); vy = fmaxf(vy, 0.f); }
                *(float2*)(C + (size_t)cr * NDIM + col) = make_float2(vx, vy);
            }
        }
    }
}

// ---------------------------------------------------------------------------
// 4) combine: out[b] = w0*y[b,0] + w1*y[b,1]
// ---------------------------------------------------------------------------
__global__ __launch_bounds__(256)
void combine_kernel(float* __restrict__ out) {
    int i = blockIdx.x * blockDim.x + threadIdx.x;   // float4 index
    const int per_tok = DOUT / 4;
    if (i >= NTOK * per_tok) return;
    int b = i / per_tok;
    int c = i - b * per_tok;
    float w0 = g_tw[b * 2 + 0];
    float w1 = g_tw[b * 2 + 1];
    float4 a = ((const float4*)(g_y + (size_t)(b * 2 + 0) * DOUT))[c];
    float4 d = ((const float4*)(g_y + (size_t)(b * 2 + 1) * DOUT))[c];
    float4 r;
    r.x = w0 * a.x + w1 * d.x;
    r.y = w0 * a.y + w1 * d.y;
    r.z = w0 * a.z + w1 * d.z;
    r.w = w0 * a.w + w1 * d.w;
    ((float4*)out)[i] = r;
}

// ---------------------------------------------------------------------------
extern "C" void kernel_launch(void* const* d_in, const int* in_sizes, int n_in,
                              void* d_out, int out_size) {
    const float* x  = (const float*)d_in[0];
    const float* gw = (const float*)d_in[1];
    const float* w1 = (const float*)d_in[2];
    const float* b1 = (const float*)d_in[3];
    const float* w2 = (const float*)d_in[4];
    const float* b2 = (const float*)d_in[5];
    float* out = (float*)d_out;

    cudaFuncSetAttribute(moe_gemm_tf32<DIN, DHID, true>,
                         cudaFuncAttributeMaxDynamicSharedMemorySize, DSMEM_BYTES);
    cudaFuncSetAttribute(moe_gemm_tf32<DHID, DOUT, false>,
                         cudaFuncAttributeMaxDynamicSharedMemorySize, DSMEM_BYTES);

    float* hbuf;
    cudaGetSymbolAddress((void**)&hbuf, g_h);

    init_kernel<<<1, 32>>>();
    gate_kernel<<<NTOK, 128>>>(x, gw);

    // phase 1: h = relu(x @ w1^T + b1)   (A = x, fp32 direct)
    moe_gemm_tf32<DIN, DHID, true>
        <<<dim3(CAP / 128, DHID / 128, NEXP), 256, DSMEM_BYTES>>>(x, w1, b1);

    // phase 2: y = h @ w2^T + b2         (A = h, fp32 direct)
    moe_gemm_tf32<DHID, DOUT, false>
        <<<dim3(CAP / 128, DOUT / 128, NEXP), 256, DSMEM_BYTES>>>(hbuf, w2, b2);

    combine_kernel<<<(NTOK * DOUT / 4 + 255) / 256, 256>>>(out);
}

// round 16
// speedup vs baseline: 3.5901x; 1.0344x over previous
#include <cuda_runtime.h>
#include <cuda_bf16.h>
#include <cstdint>

// Problem constants (MoE_TopK: E=16, K=2, B=4096, D_IN=1024, D_HID=2048, D_OUT=1024)
#define NTOK  4096
#define NEXP  16
#define DIN   1024
#define DHID  2048
#define DOUT  1024
#define CAP   4096   // worst-case tokens per expert

// Scratch (no allocations allowed -> __device__ globals)
__device__ int   g_cnt[NEXP];
__device__ int   g_tok[NEXP * CAP];
__device__ int   g_slot[NEXP * CAP];
__device__ float g_tw[NTOK * 2];
__device__ float g_xr[NTOK * DIN];       // tf32-rounded x (16 MB)
__device__ float g_h[NTOK * 2 * DHID];   // tf32-rounded hidden (64 MB)
__device__ float g_y[NTOK * 2 * DOUT];   // 32 MB

// ---------------------------------------------------------------------------
// helpers (base sm_103 ISA: mma.sync tf32 + cp.async)
// ---------------------------------------------------------------------------
__device__ __forceinline__ uint32_t smem_u32(const void* p) {
    uint32_t a;
    asm("{ .reg .u64 t; cvta.to.shared.u64 t, %1; cvt.u32.u64 %0, t; }"
        : "=r"(a) : "l"(p));
    return a;
}

// plain shared load (operand already tf32-rounded in gmem)
__device__ __forceinline__ uint32_t lds32(uint32_t addr) {
    uint32_t v;
    asm volatile("ld.shared.b32 %0, [%1];" : "=r"(v) : "r"(addr));
    return v;
}

// shared load + unbiased round-to-nearest tf32 conversion (B side / weights)
__device__ __forceinline__ uint32_t lds_tf32(uint32_t addr) {
    uint32_t v;
    asm volatile("{ .reg .b32 t; ld.shared.b32 t, [%1]; cvt.rna.tf32.f32 %0, t; }"
                 : "=r"(v) : "r"(addr));
    return v;
}

// round fp32 -> tf32-representable fp32 (bit pattern stays valid fp32)
__device__ __forceinline__ float rnd_tf32(float x) {
    uint32_t v;
    asm("cvt.rna.tf32.f32 %0, %1;" : "=r"(v) : "f"(x));
    return __uint_as_float(v);
}

__device__ __forceinline__ void mma_tf32(float* c, const uint32_t* a,
                                         uint32_t b0, uint32_t b1) {
    asm volatile("mma.sync.aligned.m16n8k8.row.col.f32.tf32.tf32.f32 "
                 "{%0,%1,%2,%3}, {%4,%5,%6,%7}, {%8,%9}, {%0,%1,%2,%3};"
                 : "+f"(c[0]), "+f"(c[1]), "+f"(c[2]), "+f"(c[3])
                 : "r"(a[0]), "r"(a[1]), "r"(a[2]), "r"(a[3]), "r"(b0), "r"(b1));
}

__device__ __forceinline__ void cp16(uint32_t dst, const void* src, int src_bytes) {
    asm volatile("cp.async.cg.shared.global [%0], [%1], 16, %2;"
                 :: "r"(dst), "l"(src), "r"(src_bytes));
}
__device__ __forceinline__ void cp_commit() {
    asm volatile("cp.async.commit_group;");
}
template<int N>
__device__ __forceinline__ void cp_wait() {
    asm volatile("cp.async.wait_group %0;" :: "n"(N));
}

// ---------------------------------------------------------------------------
// 0) zero per-expert counters (graph replays)
// ---------------------------------------------------------------------------
__global__ void init_kernel() {
    if (threadIdx.x < NEXP) g_cnt[threadIdx.x] = 0;
}

// ---------------------------------------------------------------------------
// 1) gating: scores, top-2, softmax, route; also writes tf32-rounded x copy
// ---------------------------------------------------------------------------
__global__ __launch_bounds__(128)
void gate_kernel(const float* __restrict__ x, const float* __restrict__ gw) {
    __shared__ float xs[DIN];
    __shared__ float sc[NEXP];

    const int b = blockIdx.x;
    const float4* xg  = (const float4*)(x + (size_t)b * DIN);
    float4*       xs4 = (float4*)xs;
    for (int i = threadIdx.x; i < DIN / 4; i += blockDim.x) xs4[i] = xg[i];
    __syncthreads();

    // tf32-rounded copy of the row (removes cvt from GEMM A-side reads)
    for (int i = threadIdx.x; i < DIN / 4; i += blockDim.x) {
        float4 v = xs4[i];
        v.x = rnd_tf32(v.x); v.y = rnd_tf32(v.y);
        v.z = rnd_tf32(v.z); v.w = rnd_tf32(v.w);
        ((float4*)(g_xr + (size_t)b * DIN))[i] = v;
    }

    const int warp = threadIdx.x >> 5;
    const int lane = threadIdx.x & 31;
    for (int e = warp; e < NEXP; e += 4) {
        const float* w = gw + (size_t)e * DIN;
        float s = 0.f;
        for (int i = lane; i < DIN; i += 32) s += xs[i] * __ldg(&w[i]);
        #pragma unroll
        for (int o = 16; o > 0; o >>= 1) s += __shfl_xor_sync(0xffffffffu, s, o);
        if (lane == 0) sc[e] = s;
    }
    __syncthreads();

    if (threadIdx.x == 0) {
        int i0 = 0; float v0 = sc[0];
        #pragma unroll
        for (int e = 1; e < NEXP; e++) if (sc[e] > v0) { v0 = sc[e]; i0 = e; }
        int i1 = -1; float v1 = -3.4e38f;
        #pragma unroll
        for (int e = 0; e < NEXP; e++)
            if (e != i0 && sc[e] > v1) { v1 = sc[e]; i1 = e; }

        float e1  = __expf(v1 - v0);
        float inv = 1.f / (1.f + e1);
        g_tw[b * 2 + 0] = inv;
        g_tw[b * 2 + 1] = e1 * inv;

        int p0 = atomicAdd(&g_cnt[i0], 1);
        g_tok[i0 * CAP + p0]  = b;
        g_slot[i0 * CAP + p0] = 0;
        int p1 = atomicAdd(&g_cnt[i1], 1);
        g_tok[i1 * CAP + p1]  = b;
        g_slot[i1 * CAP + p1] = 1;
    }
}

// ---------------------------------------------------------------------------
// 2)+3) grouped tf32 HMMA GEMM.
//    CTA tile 128m x 256n, 8 warps (2x4), warp tile 64x64.
//    K-chunk 32, 3-stage cp.async pipeline, 1 CTA/SM (162 KB smem, ~190 regs).
//    A pre-rounded (plain lds), B (weights) cvt-at-read.
//    Rows padded to 144 B (36 floats == 4 mod 32 banks -> conflict-free).
// ---------------------------------------------------------------------------
#define KC          32
#define ROW_B       144
#define A_ROWS      128
#define B_ROWS      256
#define A_TILE_B    (A_ROWS * ROW_B)               // 18432
#define STAGE_BYTES ((A_ROWS + B_ROWS) * ROW_B)    // 55296
#define NSTAGE      3
#define DSMEM_BYTES (NSTAGE * STAGE_BYTES)         // 165888

template<int KDIM, int NDIM, bool PHASE1>
__global__ __launch_bounds__(256, 1)
void moe_gemm_tf32(const float* __restrict__ A_g,     // g_xr (p1) / g_h (p2)
                   const float* __restrict__ W,       // [NEXP, NDIM, KDIM]
                   const float* __restrict__ bias)    // [NEXP, NDIM]
{
    extern __shared__ char dsm[];
    __shared__ int srow[128];
    __shared__ int scrow[128];

    const int e   = blockIdx.z;
    const int n_e = g_cnt[e];
    const int m0  = blockIdx.x * 128;
    if (m0 >= n_e) return;                          // dead tile
    const int n0  = blockIdx.y * 256;

    const float* Wb = W + (size_t)e * NDIM * KDIM;

    const int tid = threadIdx.x;
    if (tid < 128) {
        int p = m0 + tid;
        if (p < n_e) {
            int tok  = g_tok[e * CAP + p];
            int slot = g_slot[e * CAP + p];
            srow[tid]  = PHASE1 ? tok : (tok * 2 + slot);
            scrow[tid] = tok * 2 + slot;
        } else { srow[tid] = -1; scrow[tid] = -1; }
    }
    __syncthreads();

    const uint32_t sbase = smem_u32(dsm);

    // ---- loader: A 128 rows + B 256 rows x 32 fp32 = 3072 16B chunks ----
    auto load_stage = [&](int s, int k0) {
        const uint32_t stb = sbase + s * STAGE_BYTES;
        #pragma unroll
        for (int i = 0; i < 12; i++) {
            int f = tid + i * 256;                 // 0..3071
            const float* src;
            uint32_t dst;
            int sz = 16;
            if (f < A_ROWS * 8) {
                int rr = f >> 3, ch = f & 7;
                int ar = srow[rr];
                if (ar < 0) { ar = 0; sz = 0; }
                src = A_g + (size_t)ar * KDIM + k0 + ch * 4;
                dst = stb + rr * ROW_B + ch * 16;
            } else {
                int fb = f - A_ROWS * 8;
                int rr = fb >> 3, ch = fb & 7;
                src = Wb + (size_t)(n0 + rr) * KDIM + k0 + ch * 4;
                dst = stb + A_TILE_B + rr * ROW_B + ch * 16;
            }
            cp16(dst, src, sz);
        }
        cp_commit();
    };

    const int w   = tid >> 5;
    const int t   = tid & 31;
    const int m0w = (w & 1) * 64;      // warp M offset (2 in m)
    const int n0w = (w >> 1) * 64;     // warp N offset (4 in n)
    const int g   = t >> 2;            // group id 0..7
    const int tig = t & 3;             // thread-in-group

    float acc[4][8][4];
    #pragma unroll
    for (int mi = 0; mi < 4; mi++)
        #pragma unroll
        for (int nf = 0; nf < 8; nf++)
            #pragma unroll
            for (int j = 0; j < 4; j++) acc[mi][nf][j] = 0.f;

    constexpr int NC = KDIM / KC;

    load_stage(0, 0);
    load_stage(1, KC);

    int slot = 0;
    for (int c = 0; c < NC; c++) {
        if (c == NC - 1) cp_wait<0>(); else cp_wait<1>();
        __syncthreads();

        if (c + 2 < NC) {
            int ns = slot + 2; if (ns >= NSTAGE) ns -= NSTAGE;
            load_stage(ns, (c + 2) * KC);
        }

        const uint32_t stb = sbase + slot * STAGE_BYTES;
        const uint32_t sA  = stb;
        const uint32_t sB  = stb + A_TILE_B;

        #pragma unroll
        for (int ks = 0; ks < 4; ks++) {
            const int kb = ks * 8;
            // A fragments (pre-rounded -> plain lds):
            // a0:(g,tig) a1:(g+8,tig) a2:(g,tig+4) a3:(g+8,tig+4)
            uint32_t Af[4][4];
            #pragma unroll
            for (int mi = 0; mi < 4; mi++) {
                uint32_t r0 = sA + (uint32_t)(m0w + 16 * mi + g) * ROW_B
                                 + (uint32_t)(kb + tig) * 4u;
                Af[mi][0] = lds32(r0);
                Af[mi][1] = lds32(r0 + 8u * ROW_B);
                Af[mi][2] = lds32(r0 + 16u);
                Af[mi][3] = lds32(r0 + 8u * ROW_B + 16u);
            }
            // B fragments (weights, cvt at read): b0:(k=tig,n=g) b1:(k=tig+4,n=g)
            #pragma unroll
            for (int nf = 0; nf < 8; nf++) {
                uint32_t rb = sB + (uint32_t)(n0w + 8 * nf + g) * ROW_B
                                 + (uint32_t)(kb + tig) * 4u;
                uint32_t b0 = lds_tf32(rb);
                uint32_t b1 = lds_tf32(rb + 16u);
                #pragma unroll
                for (int mi = 0; mi < 4; mi++)
                    mma_tf32(acc[mi][nf], Af[mi], b0, b1);
            }
        }
        if (++slot == NSTAGE) slot = 0;
    }

    // ---- epilogue: bias (+relu+tf32-round phase1), scatter rows ----
    const int tcol = tig * 2;
    float2 bb[8];
    #pragma unroll
    for (int nf = 0; nf < 8; nf++)
        bb[nf] = *(const float2*)(bias + (size_t)e * NDIM + n0 + n0w + nf * 8 + tcol);

    float* C = PHASE1 ? g_h : g_y;
    #pragma unroll
    for (int mi = 0; mi < 4; mi++) {
        const int ml  = m0w + 16 * mi + g;
        const int cr0 = scrow[ml];
        const int cr1 = scrow[ml + 8];
        #pragma unroll
        for (int nf = 0; nf < 8; nf++) {
            const int col = n0 + n0w + nf * 8 + tcol;
            float* a = acc[mi][nf];
            #pragma unroll
            for (int h = 0; h < 2; h++) {
                const int cr = h ? cr1 : cr0;
                if (cr < 0) continue;
                float vx = a[2 * h + 0] + bb[nf].x;
                float vy = a[2 * h + 1] + bb[nf].y;
                if (PHASE1) {
                    vx = rnd_tf32(fmaxf(vx, 0.f));   // pre-round h for phase2 A
                    vy = rnd_tf32(fmaxf(vy, 0.f));
                }
                *(float2*)(C + (size_t)cr * NDIM + col) = make_float2(vx, vy);
            }
        }
    }
}

// ---------------------------------------------------------------------------
// 4) combine: out[b] = w0*y[b,0] + w1*y[b,1]
// ---------------------------------------------------------------------------
__global__ __launch_bounds__(256)
void combine_kernel(float* __restrict__ out) {
    int i = blockIdx.x * blockDim.x + threadIdx.x;   // float4 index
    const int per_tok = DOUT / 4;
    if (i >= NTOK * per_tok) return;
    int b = i / per_tok;
    int c = i - b * per_tok;
    float w0 = g_tw[b * 2 + 0];
    float w1 = g_tw[b * 2 + 1];
    float4 a = ((const float4*)(g_y + (size_t)(b * 2 + 0) * DOUT))[c];
    float4 d = ((const float4*)(g_y + (size_t)(b * 2 + 1) * DOUT))[c];
    float4 r;
    r.x = w0 * a.x + w1 * d.x;
    r.y = w0 * a.y + w1 * d.y;
    r.z = w0 * a.z + w1 * d.z;
    r.w = w0 * a.w + w1 * d.w;
    ((float4*)out)[i] = r;
}

// ---------------------------------------------------------------------------
extern "C" void kernel_launch(void* const* d_in, const int* in_sizes, int n_in,
                              void* d_out, int out_size) {
    const float* x  = (const float*)d_in[0];
    const float* gw = (const float*)d_in[1];
    const float* w1 = (const float*)d_in[2];
    const float* b1 = (const float*)d_in[3];
    const float* w2 = (const float*)d_in[4];
    const float* b2 = (const float*)d_in[5];
    float* out = (float*)d_out;

    cudaFuncSetAttribute(moe_gemm_tf32<DIN, DHID, true>,
                         cudaFuncAttributeMaxDynamicSharedMemorySize, DSMEM_BYTES);
    cudaFuncSetAttribute(moe_gemm_tf32<DHID, DOUT, false>,
                         cudaFuncAttributeMaxDynamicSharedMemorySize, DSMEM_BYTES);

    float *xr, *hbuf;
    cudaGetSymbolAddress((void**)&xr,   g_xr);
    cudaGetSymbolAddress((void**)&hbuf, g_h);

    init_kernel<<<1, 32>>>();
    gate_kernel<<<NTOK, 128>>>(x, gw);

    // phase 1: h = relu(x @ w1^T + b1)   (A = rounded x)
    moe_gemm_tf32<DIN, DHID, true>
        <<<dim3(CAP / 128, DHID / 256, NEXP), 256, DSMEM_BYTES>>>(xr, w1, b1);

    // phase 2: y = h @ w2^T + b2         (A = rounded h)
    moe_gemm_tf32<DHID, DOUT, false>
        <<<dim3(CAP / 128, DOUT / 256, NEXP), 256, DSMEM_BYTES>>>(hbuf, w2, b2);

    combine_kernel<<<(NTOK * DOUT / 4 + 255) / 256, 256>>>(out);
}